// round 12
// baseline (speedup 1.0000x reference)
#include <cuda_runtime.h>
#include <cuda_bf16.h>
#include <cstdint>

// Embedding gather via double-buffered bulk-async TMA.
// Each CTA handles 8 rows (32 KB) as two 16 KB stages:
//   issue loads(stage0); issue loads(stage1); wait0; store0 (one 16KB bulk);
//   wait1; store1 (one 16KB bulk).
// Output rows per stage are contiguous -> single maximal bulk store each.

#define ROW_BYTES 4096
#define ROWS      8              // rows per CTA
#define STAGE     4              // rows per stage
#define STAGE_BYTES (STAGE * ROW_BYTES)   // 16 KB
#define DIM       1024

__device__ __forceinline__ uint32_t smem_u32(const void* p) {
    return (uint32_t)__cvta_generic_to_shared(p);
}

__device__ __forceinline__ void mbar_wait(uint32_t mb) {
    uint32_t done;
    asm volatile(
        "{\n\t.reg .pred p;\n\t"
        "mbarrier.try_wait.parity.shared.b64 p, [%1], 0;\n\t"
        "selp.b32 %0, 1, 0, p;\n\t}"
        : "=r"(done) : "r"(mb) : "memory");
    while (!done) {
        asm volatile(
            "{\n\t.reg .pred p;\n\t"
            "mbarrier.try_wait.parity.shared.b64 p, [%1], 0, 0x989680;\n\t"
            "selp.b32 %0, 1, 0, p;\n\t}"
            : "=r"(done) : "r"(mb) : "memory");
    }
}

__global__ void __launch_bounds__(32)
embedding_tma2_kernel(const int* __restrict__ token_ids,
                      const char* __restrict__ e,     // [32000, 4096 B]
                      char* __restrict__ out,         // [n_tok, 4096 B]
                      int n_tok)
{
    __shared__ alignas(128) char buf[2][STAGE_BYTES];  // 2 x 16 KB
    __shared__ alignas(8)   uint64_t mbar[2];

    if (threadIdx.x != 0) return;

    const int row0 = blockIdx.x * ROWS;                // n_tok % ROWS == 0

    const uint32_t mb0 = smem_u32(&mbar[0]);
    const uint32_t mb1 = smem_u32(&mbar[1]);
    asm volatile("mbarrier.init.shared.b64 [%0], 1;" :: "r"(mb0) : "memory");
    asm volatile("mbarrier.init.shared.b64 [%0], 1;" :: "r"(mb1) : "memory");
    asm volatile("fence.proxy.async.shared::cta;" ::: "memory");

    // Load all 8 token ids up front (independent LDGs).
    int toks[ROWS];
#pragma unroll
    for (int r = 0; r < ROWS; r++)
        toks[r] = __ldg(&token_ids[row0 + r]);

    const uint64_t e_base   = (uint64_t)__cvta_generic_to_global(e);
    const uint64_t out_base = (uint64_t)__cvta_generic_to_global(out) +
                              (uint64_t)row0 * ROW_BYTES;

    // Issue BOTH stages' gather loads back-to-back (deep TMA queue).
#pragma unroll
    for (int s = 0; s < 2; s++) {
        const uint32_t mb = s ? mb1 : mb0;
        asm volatile("mbarrier.arrive.expect_tx.shared.b64 _, [%0], %1;"
                     :: "r"(mb), "r"((uint32_t)STAGE_BYTES) : "memory");
#pragma unroll
        for (int r = 0; r < STAGE; r++) {
            const uint64_t src = e_base +
                (uint64_t)toks[s * STAGE + r] * ROW_BYTES;
            const uint32_t dst = smem_u32(&buf[s][r * ROW_BYTES]);
            asm volatile(
                "cp.async.bulk.shared::cta.global.mbarrier::complete_tx::bytes "
                "[%0], [%1], %2, [%3];"
                :: "r"(dst), "l"(src), "r"((uint32_t)ROW_BYTES), "r"(mb)
                : "memory");
        }
    }

    // Stage 0: wait, single contiguous 16 KB bulk store.
    mbar_wait(mb0);
    asm volatile(
        "cp.async.bulk.global.shared::cta.bulk_group [%0], [%1], %2;"
        :: "l"(out_base), "r"(smem_u32(buf[0])), "r"((uint32_t)STAGE_BYTES)
        : "memory");
    asm volatile("cp.async.bulk.commit_group;" ::: "memory");

    // Stage 1: wait, single contiguous 16 KB bulk store.
    mbar_wait(mb1);
    asm volatile(
        "cp.async.bulk.global.shared::cta.bulk_group [%0], [%1], %2;"
        :: "l"(out_base + STAGE_BYTES), "r"(smem_u32(buf[1])),
           "r"((uint32_t)STAGE_BYTES)
        : "memory");
    asm volatile("cp.async.bulk.commit_group;" ::: "memory");
    asm volatile("cp.async.bulk.wait_group 0;" ::: "memory");
}

extern "C" void kernel_launch(void* const* d_in, const int* in_sizes, int n_in,
                              void* d_out, int out_size)
{
    // Robust to input ordering: token_ids is the small int32 buffer,
    // e is the large fp32 table.
    const int* token_ids;
    const char* e;
    if (n_in >= 2 && in_sizes[0] > in_sizes[1]) {
        e         = (const char*)d_in[0];
        token_ids = (const int*)d_in[1];
    } else {
        token_ids = (const int*)d_in[0];
        e         = (const char*)d_in[1];
    }
    char* out = (char*)d_out;

    const int n_tok = out_size / DIM;                   // 8192
    const int grid  = n_tok / ROWS;                     // 1024
    embedding_tma2_kernel<<<grid, 32>>>(token_ids, e, out, n_tok);
}

// round 16
// speedup vs baseline: 1.1131x; 1.1131x over previous
#include <cuda_runtime.h>
#include <cuda_bf16.h>
#include <cstdint>

// Embedding gather via bulk-async TMA (best-measured structure, R7):
// grid=2048, 32-thread CTAs, 4 rows x 4KB per CTA, 16KB smem.
// Refinement: all 4 token-index LDGs are issued before the TMA sequence so
// index-load latency overlaps instead of serializing with TMA issues.

#define ROW_BYTES 4096          // 1024 fp32
#define ROWS      4             // rows per CTA
#define DIM       1024

__device__ __forceinline__ uint32_t smem_u32(const void* p) {
    return (uint32_t)__cvta_generic_to_shared(p);
}

__global__ void __launch_bounds__(32)
embedding_tma_kernel(const int* __restrict__ token_ids,
                     const char* __restrict__ e,     // [32000, 4096 B]
                     char* __restrict__ out,         // [n_tok, 4096 B]
                     int n_tok)
{
    __shared__ alignas(128) char buf[ROWS * ROW_BYTES];
    __shared__ alignas(8)   uint64_t mbar;

    if (threadIdx.x != 0) return;     // single-thread control; TMA moves data

    const int row0 = blockIdx.x * ROWS;        // n_tok % ROWS == 0 (8192/4)

    // Front-issue all index loads (independent, overlap their latency).
    int toks[ROWS];
#pragma unroll
    for (int r = 0; r < ROWS; r++)
        toks[r] = __ldg(&token_ids[row0 + r]);

    // Init mbarrier, publish to async proxy.
    const uint32_t mb = smem_u32(&mbar);
    asm volatile("mbarrier.init.shared.b64 [%0], 1;" :: "r"(mb) : "memory");
    asm volatile("fence.proxy.async.shared::cta;" ::: "memory");

    // Expect all bytes, then issue the 4 gather loads back-to-back.
    asm volatile("mbarrier.arrive.expect_tx.shared.b64 _, [%0], %1;"
                 :: "r"(mb), "r"((uint32_t)(ROWS * ROW_BYTES)) : "memory");

    const uint64_t e_base = (uint64_t)__cvta_generic_to_global(e);
#pragma unroll
    for (int r = 0; r < ROWS; r++) {
        const uint64_t src = e_base + (uint64_t)toks[r] * ROW_BYTES;
        const uint32_t dst = smem_u32(buf + r * ROW_BYTES);
        asm volatile(
            "cp.async.bulk.shared::cta.global.mbarrier::complete_tx::bytes "
            "[%0], [%1], %2, [%3];"
            :: "r"(dst), "l"(src), "r"((uint32_t)ROW_BYTES), "r"(mb)
            : "memory");
    }

    // Wait for all loads (phase 0).
    {
        uint32_t done;
        asm volatile(
            "{\n\t.reg .pred p;\n\t"
            "mbarrier.try_wait.parity.shared.b64 p, [%1], 0;\n\t"
            "selp.b32 %0, 1, 0, p;\n\t}"
            : "=r"(done) : "r"(mb) : "memory");
        while (!done) {
            asm volatile(
                "{\n\t.reg .pred p;\n\t"
                "mbarrier.try_wait.parity.shared.b64 p, [%1], 0, 0x989680;\n\t"
                "selp.b32 %0, 1, 0, p;\n\t}"
                : "=r"(done) : "r"(mb) : "memory");
        }
    }

    // One contiguous 16 KB bulk store (CTA's output rows are contiguous).
    const uint64_t dst = (uint64_t)__cvta_generic_to_global(out) +
                         (uint64_t)row0 * ROW_BYTES;
    asm volatile(
        "cp.async.bulk.global.shared::cta.bulk_group [%0], [%1], %2;"
        :: "l"(dst), "r"(smem_u32(buf)), "r"((uint32_t)(ROWS * ROW_BYTES))
        : "memory");
    asm volatile("cp.async.bulk.commit_group;" ::: "memory");
    asm volatile("cp.async.bulk.wait_group 0;" ::: "memory");
}

extern "C" void kernel_launch(void* const* d_in, const int* in_sizes, int n_in,
                              void* d_out, int out_size)
{
    // Robust to input ordering: token_ids is the small int32 buffer,
    // e is the large fp32 table.
    const int* token_ids;
    const char* e;
    if (n_in >= 2 && in_sizes[0] > in_sizes[1]) {
        e         = (const char*)d_in[0];
        token_ids = (const int*)d_in[1];
    } else {
        token_ids = (const int*)d_in[0];
        e         = (const char*)d_in[1];
    }
    char* out = (char*)d_out;

    const int n_tok = out_size / DIM;                   // 8192
    const int grid  = n_tok / ROWS;                     // 2048
    embedding_tma_kernel<<<grid, 32>>>(token_ids, e, out, n_tok);
}